// round 15
// baseline (speedup 1.0000x reference)
#include <cuda_runtime.h>
#include <cuda_bf16.h>
#include <cstdint>

typedef unsigned long long ull;
union F2 { float2 f; ull u; };

#define Bb 64
#define Tt 512
#define Hh 1024
#define G4 4096
#define KE 3072
#define HSEQ_N (Bb*Tt*Hh)

// scratch (device globals: allocation-free rule)
__device__ float g_xp[(size_t)Bb * Tt * G4];          // 512 MB x_proj
__device__ __nv_bfloat16 g_abf[(size_t)Bb * Tt * KE]; // 192 MB  A' = [hi, lo, hi]
__device__ __nv_bfloat16 g_wbf[(size_t)G4 * KE];      // 24 MB   W' = [hi, hi, lo]
__device__ __nv_bfloat16 g_hh[2][Bb * Hh];            // h hi, double-buffered
__device__ __nv_bfloat16 g_hl[2][Bb * Hh];            // h lo
__device__ unsigned g_bar_count;
__device__ unsigned g_bar_gen;

__device__ __forceinline__ uint32_t smem_u32(const void* p) {
    uint32_t a;
    asm("{ .reg .u64 t; cvta.to.shared.u64 t, %1; cvt.u32.u64 %0, t; }" : "=r"(a) : "l"(p));
    return a;
}

#define LDMX4(r0,r1,r2,r3,addr) \
    asm volatile("ldmatrix.sync.aligned.m8n8.x4.shared.b16 {%0,%1,%2,%3}, [%4];" \
        : "=r"(r0), "=r"(r1), "=r"(r2), "=r"(r3) : "r"(addr))

#define MMA16816(d,a0,a1,a2,a3,b0,b1) \
    asm volatile("mma.sync.aligned.m16n8k16.row.col.f32.bf16.bf16.f32 " \
        "{%0,%1,%2,%3}, {%4,%5,%6,%7}, {%8,%9}, {%0,%1,%2,%3};" \
        : "+f"((d)[0]), "+f"((d)[1]), "+f"((d)[2]), "+f"((d)[3]) \
        : "r"(a0), "r"(a1), "r"(a2), "r"(a3), "r"(b0), "r"(b1))

__device__ __forceinline__ float sigf(float x) { return 1.0f / (1.0f + __expf(-x)); }

// ---------------------------------------------------------------------------
// bf16-split conversions
// ---------------------------------------------------------------------------
__global__ __launch_bounds__(256) void conv_a_kernel(const float* __restrict__ x)
{
    size_t base = ((size_t)blockIdx.x * 256 + threadIdx.x) * 2;
    int m = (int)(base >> 10), k = (int)(base & 1023);
    float2 a = *(const float2*)(x + base);
    __nv_bfloat16 h0 = __float2bfloat16(a.x);
    __nv_bfloat16 h1 = __float2bfloat16(a.y);
    __nv_bfloat16 l0 = __float2bfloat16(a.x - __bfloat162float(h0));
    __nv_bfloat16 l1 = __float2bfloat16(a.y - __bfloat162float(h1));
    __nv_bfloat162 hh; hh.x = h0; hh.y = h1;
    __nv_bfloat162 ll; ll.x = l0; ll.y = l1;
    __nv_bfloat16* dst = g_abf + (size_t)m * KE + k;
    *(__nv_bfloat162*)(dst)        = hh;
    *(__nv_bfloat162*)(dst + 1024) = ll;
    *(__nv_bfloat162*)(dst + 2048) = hh;
}

__global__ __launch_bounds__(256) void conv_w_kernel(
    const float* __restrict__ W0, const float* __restrict__ W1,
    const float* __restrict__ W2, const float* __restrict__ W3)
{
    size_t base = ((size_t)blockIdx.x * 256 + threadIdx.x) * 2;
    int n = (int)(base >> 10), k = (int)(base & 1023);
    int q = n >> 10;
    const float* W = (q == 0) ? W0 : (q == 1) ? W1 : (q == 2) ? W2 : W3;
    float2 a = *(const float2*)(W + (size_t)(n & 1023) * 1024 + k);
    __nv_bfloat16 h0 = __float2bfloat16(a.x);
    __nv_bfloat16 h1 = __float2bfloat16(a.y);
    __nv_bfloat16 l0 = __float2bfloat16(a.x - __bfloat162float(h0));
    __nv_bfloat16 l1 = __float2bfloat16(a.y - __bfloat162float(h1));
    __nv_bfloat162 hh; hh.x = h0; hh.y = h1;
    __nv_bfloat162 ll; ll.x = l0; ll.y = l1;
    __nv_bfloat16* dst = g_wbf + (size_t)n * KE + k;
    *(__nv_bfloat162*)(dst)        = hh;
    *(__nv_bfloat162*)(dst + 1024) = hh;
    *(__nv_bfloat162*)(dst + 2048) = ll;
}

__global__ __launch_bounds__(256) void conv_h0_kernel(const float* __restrict__ h0)
{
    int i = blockIdx.x * 256 + threadIdx.x;     // 65536 elems
    float v = h0[i];
    __nv_bfloat16 h = __float2bfloat16(v);
    g_hh[0][i] = h;
    g_hl[0][i] = __float2bfloat16(v - __bfloat162float(h));
}

// ---------------------------------------------------------------------------
// mma.sync bf16 GEMM for x_proj (validated; 2 CTAs/SM) — unchanged from R14
// ---------------------------------------------------------------------------
__global__ __launch_bounds__(256, 2) void gemm_mma(
    const float* __restrict__ b0, const float* __restrict__ b1,
    const float* __restrict__ b2, const float* __restrict__ b3)
{
    __shared__ __align__(128) char smA[2][8192];
    __shared__ __align__(128) char smB[2][8192];

    const int tid = threadIdx.x, wid = tid >> 5, lane = tid & 31;
    const int mTile = blockIdx.x >> 5, nTile = blockIdx.x & 31;
    const int m0 = mTile * 128, n0 = nTile * 128;
    const int m_w = (wid & 3) * 32;
    const int n_wb = (wid >> 2) * 64;

    const uint32_t sA = smem_u32(smA);
    const uint32_t sB = smem_u32(smB);

    const int r0i = tid >> 2, s0 = tid & 3;
    const int r1i = (tid + 256) >> 2, s1 = (tid + 256) & 3;
    const uint32_t st0 = (uint32_t)((r0i >> 1) * 128 + ((((r0i & 1) * 4 + s0) ^ ((r0i >> 1) & 7)) * 16));
    const uint32_t st1 = (uint32_t)((r1i >> 1) * 128 + ((((r1i & 1) * 4 + s1) ^ ((r1i >> 1) & 7)) * 16));
    const __nv_bfloat16* gA0 = g_abf + (size_t)(m0 + r0i) * KE + s0 * 8;
    const __nv_bfloat16* gA1 = g_abf + (size_t)(m0 + r1i) * KE + s1 * 8;
    const __nv_bfloat16* gB0 = g_wbf + (size_t)(n0 + r0i) * KE + s0 * 8;
    const __nv_bfloat16* gB1 = g_wbf + (size_t)(n0 + r1i) * KE + s1 * 8;

    const int row_l = lane & 15, sh = lane >> 4;
    uint32_t offA[2], offB[4];
    #pragma unroll
    for (int a = 0; a < 2; a++) {
        int r = m_w + a * 16 + row_l;
        int L = r >> 1, p = (r & 1) * 4 + sh;
        offA[a] = (uint32_t)(L * 128 + ((p ^ (L & 7)) * 16));
    }
    #pragma unroll
    for (int b = 0; b < 4; b++) {
        int r = n_wb + b * 16 + row_l;
        int L = r >> 1, p = (r & 1) * 4 + sh;
        offB[b] = (uint32_t)(L * 128 + ((p ^ (L & 7)) * 16));
    }

    float acc[2][8][4];
    #pragma unroll
    for (int a = 0; a < 2; a++)
        #pragma unroll
        for (int n = 0; n < 8; n++)
            #pragma unroll
            for (int c = 0; c < 4; c++) acc[a][n][c] = 0.0f;

    *(uint4*)(smA[0] + st0) = *(const uint4*)(gA0);
    *(uint4*)(smA[0] + st1) = *(const uint4*)(gA1);
    *(uint4*)(smB[0] + st0) = *(const uint4*)(gB0);
    *(uint4*)(smB[0] + st1) = *(const uint4*)(gB1);
    __syncthreads();

    int buf = 0;
    for (int ch = 0; ch < 96; ch++) {
        if (ch < 95) {
            const int nb = buf ^ 1;
            const int ko = (ch + 1) * 32;
            *(uint4*)(smA[nb] + st0) = *(const uint4*)(gA0 + ko);
            *(uint4*)(smA[nb] + st1) = *(const uint4*)(gA1 + ko);
            *(uint4*)(smB[nb] + st0) = *(const uint4*)(gB0 + ko);
            *(uint4*)(smB[nb] + st1) = *(const uint4*)(gB1 + ko);
        }
        const uint32_t bA = sA + buf * 8192;
        const uint32_t bB = sB + buf * 8192;
        #pragma unroll
        for (int ks = 0; ks < 2; ks++) {
            const uint32_t kx = ks * 32;
            uint32_t af[2][4], bf_[4][4];
            #pragma unroll
            for (int a = 0; a < 2; a++)
                LDMX4(af[a][0], af[a][1], af[a][2], af[a][3], (bA + offA[a]) ^ kx);
            #pragma unroll
            for (int b = 0; b < 4; b++)
                LDMX4(bf_[b][0], bf_[b][1], bf_[b][2], bf_[b][3], (bB + offB[b]) ^ kx);
            #pragma unroll
            for (int a = 0; a < 2; a++)
                #pragma unroll
                for (int nt = 0; nt < 8; nt++) {
                    const int bt = nt >> 1, hl = nt & 1;
                    MMA16816(acc[a][nt], af[a][0], af[a][1], af[a][2], af[a][3],
                             bf_[bt][hl], bf_[bt][hl + 2]);
                }
        }
        __syncthreads();
        buf ^= 1;
    }

    const int q = n0 >> 10;
    const float* bp = (q == 0) ? b0 : (q == 1) ? b1 : (q == 2) ? b2 : b3;
    const int nqb = (n0 & 1023) + n_wb;
    #pragma unroll
    for (int a = 0; a < 2; a++) {
        const int row0 = m0 + m_w + a * 16 + (lane >> 2);
        #pragma unroll
        for (int nt = 0; nt < 8; nt++) {
            const int col = n_wb + nt * 8 + (lane & 3) * 2;
            const float bv0 = __ldg(bp + nqb + nt * 8 + (lane & 3) * 2);
            const float bv1 = __ldg(bp + nqb + nt * 8 + (lane & 3) * 2 + 1);
            float2 v0 = make_float2(acc[a][nt][0] + bv0, acc[a][nt][1] + bv1);
            float2 v1 = make_float2(acc[a][nt][2] + bv0, acc[a][nt][3] + bv1);
            *(float2*)(g_xp + (size_t)row0 * G4 + n0 + col)       = v0;
            *(float2*)(g_xp + (size_t)(row0 + 8) * G4 + n0 + col) = v1;
        }
    }
}

// ===========================================================================
// Phase 2: persistent tensor-core scan — WARP-SPECIALIZED. 128 CTAs x 512 thr.
// Warps 0-7: MMA (exact R14 layout/frags/swizzle). Warps 8-15: staging —
// all h LDG->STS for chunk ch+1 while MMA warps compute chunk ch, taking
// global latency off the MMA critical path. Chunk = 128 k (4 sub-tiles).
// Gate math: 1 cell/thread across all 512 threads.
// ===========================================================================
#define SMS_WH 65536
#define SMS_HS 65536
#define SM_SCAN2 (2*SMS_WH + SMS_HS + 64*34*4)   // 205312

__global__ __launch_bounds__(512, 1) void lstm_scan_mma(
    const float* __restrict__ c0,
    const float* __restrict__ Whi, const float* __restrict__ Whf,
    const float* __restrict__ Whg, const float* __restrict__ Who,
    float* __restrict__ out)
{
    extern __shared__ char sm[];
    char* whh = sm;                      // Wh_hi: 32 k-chunks x 2048 B
    char* whl = sm + SMS_WH;             // Wh_lo
    char* hs  = sm + 2 * SMS_WH;         // h stage: [2 buf][hi 16K | lo 16K]
    float* gb = (float*)(sm + 2 * SMS_WH + SMS_HS);   // [64][34]

    const int tid = threadIdx.x, wid = tid >> 5, lane = tid & 31;
    const int j0 = blockIdx.x * 8;

    // ---- one-time: Wh -> smem swizzled bf16 hi/lo (512 threads: r, kt) ----
    const float* Wm[4] = {Whi, Whf, Whg, Who};
    {
        const int r = tid >> 4;          // 0..31
        const int kt = tid & 15;         // k window kt*64..+63
        const float* src = Wm[r >> 3] + (size_t)(j0 + (r & 7)) * Hh + kt * 64;
        const int L = r >> 1, rb4 = (r & 1) * 4, Lx = L & 7;
        for (int kk = 0; kk < 64; kk += 4) {
            const int k = kt * 64 + kk;
            float4 v = *(const float4*)(src + kk);
            union { __nv_bfloat16 b[4]; ull u; } uh, ul;
            #pragma unroll
            for (int e = 0; e < 4; e++) {
                float f = (&v.x)[e];
                uh.b[e] = __float2bfloat16(f);
                ul.b[e] = __float2bfloat16(f - __bfloat162float(uh.b[e]));
            }
            const int c = k >> 5, s = (k & 31) >> 3, e0 = k & 7;
            const int addr = c * 2048 + L * 128 + (((rb4 + s) ^ Lx) * 16) + e0 * 2;
            *(ull*)(whh + addr) = uh.u;
            *(ull*)(whl + addr) = ul.u;
        }
    }

    // MMA warps: ldmatrix offsets (validated formulas)
    const int row_l = lane & 15, sh = lane >> 4;
    const int m_w = (wid & 3) * 16, n_w = ((wid >> 2) & 1) * 16;
    uint32_t offA, offB;
    {
        int r = m_w + row_l;
        int L = r >> 1, p = (r & 1) * 4 + sh;
        offA = (uint32_t)(L * 128 + ((p ^ (L & 7)) * 16));
        r = n_w + row_l;
        L = r >> 1; p = (r & 1) * 4 + sh;
        offB = (uint32_t)(L * 128 + ((p ^ (L & 7)) * 16));
    }
    const uint32_t hsu = smem_u32(hs);
    const uint32_t whhu = smem_u32(whh);
    const uint32_t whlu = smem_u32(whl);

    // staging warps (wid>=8): thread stid 0..255 -> (batch sb, 16B seg ss)
    const int stid = tid - 256;
    const int sb = (stid >= 0) ? (stid >> 2) : 0, ss = (stid >= 0) ? (stid & 3) : 0;
    const uint32_t stg = (uint32_t)((sb >> 1) * 128 + ((((sb & 1) * 4 + ss) ^ ((sb >> 1) & 7)) * 16));
    const size_t gsb = (size_t)sb * Hh + ss * 8;

    // gate cells: 1 per thread (512 cells)
    const int grb = tid >> 3, grj = tid & 7;
    float creg = c0[grb * Hh + j0 + grj];
    __syncthreads();

    for (int t = 0; t < Tt; t++) {
        const int cur = t & 1, nxt = cur ^ 1;
        const __nv_bfloat16* hhp = g_hh[cur];
        const __nv_bfloat16* hlp = g_hl[cur];

        // prefetch x_proj contribution for this thread's cell
        float xq0, xq1, xq2, xq3;
        {
            const float* xb = g_xp + ((size_t)grb * Tt + t) * G4 + j0 + grj;
            xq0 = xb[0]; xq1 = xb[Hh]; xq2 = xb[2 * Hh]; xq3 = xb[3 * Hh];
        }

        float acc[3][2][4];
        #pragma unroll
        for (int tm = 0; tm < 3; tm++)
            #pragma unroll
            for (int n8 = 0; n8 < 2; n8++)
                #pragma unroll
                for (int c = 0; c < 4; c++) acc[tm][n8][c] = 0.0f;

        // stage chunk 0 (staging warps only)
        if (wid >= 8) {
            #pragma unroll
            for (int sc = 0; sc < 4; sc++) {
                *(uint4*)(hs + sc * 4096 + stg)         = *(const uint4*)(hhp + gsb + sc * 32);
                *(uint4*)(hs + 16384 + sc * 4096 + stg) = *(const uint4*)(hlp + gsb + sc * 32);
            }
        }
        __syncthreads();

        int buf = 0;
        for (int ch = 0; ch < 8; ch++) {
            if (wid >= 8) {                  // staging warps: next chunk
                if (ch < 7) {
                    const int nb = buf ^ 1;
                    #pragma unroll
                    for (int sc = 0; sc < 4; sc++) {
                        uint4 ph = *(const uint4*)(hhp + gsb + (ch + 1) * 128 + sc * 32);
                        uint4 pl = *(const uint4*)(hlp + gsb + (ch + 1) * 128 + sc * 32);
                        *(uint4*)(hs + nb * 32768 + sc * 4096 + stg)         = ph;
                        *(uint4*)(hs + nb * 32768 + 16384 + sc * 4096 + stg) = pl;
                    }
                }
            } else {                         // MMA warps: compute chunk ch
                const uint32_t bA = hsu + buf * 32768;
                #pragma unroll
                for (int sc = 0; sc < 4; sc++) {
                    const uint32_t wHc = whhu + (ch * 4 + sc) * 2048;
                    const uint32_t wLc = whlu + (ch * 4 + sc) * 2048;
                    const uint32_t aHi = bA + sc * 4096 + offA;
                    const uint32_t aLo = bA + 16384 + sc * 4096 + offA;
                    #pragma unroll
                    for (int ks = 0; ks < 2; ks++) {
                        const uint32_t kx = ks * 32;
                        uint32_t ah[4], al[4], bh[4], bl[4];
                        LDMX4(ah[0], ah[1], ah[2], ah[3], aHi ^ kx);
                        LDMX4(al[0], al[1], al[2], al[3], aLo ^ kx);
                        LDMX4(bh[0], bh[1], bh[2], bh[3], (wHc + offB) ^ kx);
                        LDMX4(bl[0], bl[1], bl[2], bl[3], (wLc + offB) ^ kx);
                        MMA16816(acc[0][0], ah[0], ah[1], ah[2], ah[3], bh[0], bh[2]);
                        MMA16816(acc[0][1], ah[0], ah[1], ah[2], ah[3], bh[1], bh[3]);
                        MMA16816(acc[1][0], al[0], al[1], al[2], al[3], bh[0], bh[2]);
                        MMA16816(acc[1][1], al[0], al[1], al[2], al[3], bh[1], bh[3]);
                        MMA16816(acc[2][0], ah[0], ah[1], ah[2], ah[3], bl[0], bl[2]);
                        MMA16816(acc[2][1], ah[0], ah[1], ah[2], ah[3], bl[1], bl[3]);
                    }
                }
            }
            __syncthreads();
            buf ^= 1;
        }

        // sum 3 terms, store warp block to gb (MMA warps only)
        if (wid < 8) {
            const int erow = m_w + (lane >> 2);
            const int ecol = n_w + (lane & 3) * 2;
            #pragma unroll
            for (int n8 = 0; n8 < 2; n8++) {
                float v0 = acc[0][n8][0] + acc[1][n8][0] + acc[2][n8][0];
                float v1 = acc[0][n8][1] + acc[1][n8][1] + acc[2][n8][1];
                float v2 = acc[0][n8][2] + acc[1][n8][2] + acc[2][n8][2];
                float v3 = acc[0][n8][3] + acc[1][n8][3] + acc[2][n8][3];
                float* q0 = gb + erow * 34 + ecol + n8 * 8;
                q0[0] = v0; q0[1] = v1;
                float* q1 = gb + (erow + 8) * 34 + ecol + n8 * 8;
                q1[0] = v2; q1[1] = v3;
            }
        }
        __syncthreads();

        // gates + state update + h hi/lo store (1 cell per thread)
        {
            const float* gr = gb + grb * 34;
            float gi = gr[grj]      + xq0;
            float gf = gr[8 + grj]  + xq1;
            float gg = gr[16 + grj] + xq2;
            float go = gr[24 + grj] + xq3;
            float iv = sigf(gi), fv = sigf(gf), ov = sigf(go);
            float gv = 2.0f * sigf(2.0f * gg) - 1.0f;
            creg = fv * creg + iv * gv;
            float hv = ov * (2.0f * sigf(2.0f * creg) - 1.0f);
            const size_t hidx = (size_t)grb * Hh + j0 + grj;
            __nv_bfloat16 hb_ = __float2bfloat16(hv);
            g_hh[nxt][hidx] = hb_;
            g_hl[nxt][hidx] = __float2bfloat16(hv - __bfloat162float(hb_));
            out[((size_t)grb * Tt + t) * Hh + j0 + grj] = hv;
            if (t == Tt - 1) {
                out[HSEQ_N + hidx] = hv;
                out[HSEQ_N + Bb * Hh + hidx] = creg;
            }
        }

        if (t < Tt - 1) {                    // grid barrier
            __syncthreads();
            if (tid == 0) {
                __threadfence();
                unsigned g = *(volatile unsigned*)&g_bar_gen;
                if (atomicAdd(&g_bar_count, 1u) == gridDim.x - 1u) {
                    atomicExch(&g_bar_count, 0u);
                    __threadfence();
                    atomicAdd(&g_bar_gen, 1u);
                } else {
                    while (*(volatile unsigned*)&g_bar_gen == g) __nanosleep(64);
                }
                __threadfence();
            }
            __syncthreads();
        }
    }
}

// ===========================================================================
extern "C" void kernel_launch(void* const* d_in, const int* in_sizes, int n_in,
                              void* d_out, int out_size)
{
    (void)in_sizes; (void)n_in; (void)out_size;
    const float* x   = (const float*)d_in[0];
    const float* h0  = (const float*)d_in[1];
    const float* c0  = (const float*)d_in[2];
    const float* Wii = (const float*)d_in[3];
    const float* Whi = (const float*)d_in[4];
    const float* bi  = (const float*)d_in[5];
    const float* Wif = (const float*)d_in[6];
    const float* Whf = (const float*)d_in[7];
    const float* bf  = (const float*)d_in[8];
    const float* Wig = (const float*)d_in[9];
    const float* Whg = (const float*)d_in[10];
    const float* bg_ = (const float*)d_in[11];
    const float* Wio = (const float*)d_in[12];
    const float* Who = (const float*)d_in[13];
    const float* bo  = (const float*)d_in[14];
    float* out = (float*)d_out;

    conv_a_kernel<<<65536, 256>>>(x);                   // A' bf16 split
    conv_w_kernel<<<8192, 256>>>(Wii, Wif, Wig, Wio);   // W' bf16 split
    conv_h0_kernel<<<256, 256>>>(h0);                   // h0 hi/lo
    gemm_mma<<<8192, 256>>>(bi, bf, bg_, bo);           // x_proj via HMMA

    static int attr_done = 0;
    if (!attr_done) {
        cudaFuncSetAttribute(lstm_scan_mma,
                             cudaFuncAttributeMaxDynamicSharedMemorySize, SM_SCAN2);
        attr_done = 1;
    }
    lstm_scan_mma<<<128, 512, SM_SCAN2>>>(c0, Whi, Whf, Whg, Who, out);
}

// round 16
// speedup vs baseline: 1.0388x; 1.0388x over previous
#include <cuda_runtime.h>
#include <cuda_bf16.h>
#include <cstdint>

typedef unsigned long long ull;
union F2 { float2 f; ull u; };

#define Bb 64
#define Tt 512
#define Hh 1024
#define G4 4096
#define KE 3072
#define HSEQ_N (Bb*Tt*Hh)

// scratch (device globals: allocation-free rule)
__device__ float g_xp[(size_t)Bb * Tt * G4];          // 512 MB x_proj
__device__ __nv_bfloat16 g_abf[(size_t)Bb * Tt * KE]; // 192 MB  A' = [hi, lo, hi]
__device__ __nv_bfloat16 g_wbf[(size_t)G4 * KE];      // 24 MB   W' = [hi, hi, lo]
__device__ __nv_bfloat16 g_hh[2][Bb * Hh];            // h hi, double-buffered
__device__ __nv_bfloat16 g_hl[2][Bb * Hh];            // h lo
__device__ unsigned g_bar_count;
__device__ unsigned g_bar_gen;

__device__ __forceinline__ uint32_t smem_u32(const void* p) {
    uint32_t a;
    asm("{ .reg .u64 t; cvta.to.shared.u64 t, %1; cvt.u32.u64 %0, t; }" : "=r"(a) : "l"(p));
    return a;
}

#define LDMX4(r0,r1,r2,r3,addr) \
    asm volatile("ldmatrix.sync.aligned.m8n8.x4.shared.b16 {%0,%1,%2,%3}, [%4];" \
        : "=r"(r0), "=r"(r1), "=r"(r2), "=r"(r3) : "r"(addr))

#define MMA16816(d,a0,a1,a2,a3,b0,b1) \
    asm volatile("mma.sync.aligned.m16n8k16.row.col.f32.bf16.bf16.f32 " \
        "{%0,%1,%2,%3}, {%4,%5,%6,%7}, {%8,%9}, {%0,%1,%2,%3};" \
        : "+f"((d)[0]), "+f"((d)[1]), "+f"((d)[2]), "+f"((d)[3]) \
        : "r"(a0), "r"(a1), "r"(a2), "r"(a3), "r"(b0), "r"(b1))

__device__ __forceinline__ float sigf(float x) { return 1.0f / (1.0f + __expf(-x)); }

// ---------------------------------------------------------------------------
// bf16-split conversions
// ---------------------------------------------------------------------------
__global__ __launch_bounds__(256) void conv_a_kernel(const float* __restrict__ x)
{
    size_t base = ((size_t)blockIdx.x * 256 + threadIdx.x) * 2;
    int m = (int)(base >> 10), k = (int)(base & 1023);
    float2 a = *(const float2*)(x + base);
    __nv_bfloat16 h0 = __float2bfloat16(a.x);
    __nv_bfloat16 h1 = __float2bfloat16(a.y);
    __nv_bfloat16 l0 = __float2bfloat16(a.x - __bfloat162float(h0));
    __nv_bfloat16 l1 = __float2bfloat16(a.y - __bfloat162float(h1));
    __nv_bfloat162 hh; hh.x = h0; hh.y = h1;
    __nv_bfloat162 ll; ll.x = l0; ll.y = l1;
    __nv_bfloat16* dst = g_abf + (size_t)m * KE + k;
    *(__nv_bfloat162*)(dst)        = hh;
    *(__nv_bfloat162*)(dst + 1024) = ll;
    *(__nv_bfloat162*)(dst + 2048) = hh;
}

__global__ __launch_bounds__(256) void conv_w_kernel(
    const float* __restrict__ W0, const float* __restrict__ W1,
    const float* __restrict__ W2, const float* __restrict__ W3)
{
    size_t base = ((size_t)blockIdx.x * 256 + threadIdx.x) * 2;
    int n = (int)(base >> 10), k = (int)(base & 1023);
    int q = n >> 10;
    const float* W = (q == 0) ? W0 : (q == 1) ? W1 : (q == 2) ? W2 : W3;
    float2 a = *(const float2*)(W + (size_t)(n & 1023) * 1024 + k);
    __nv_bfloat16 h0 = __float2bfloat16(a.x);
    __nv_bfloat16 h1 = __float2bfloat16(a.y);
    __nv_bfloat16 l0 = __float2bfloat16(a.x - __bfloat162float(h0));
    __nv_bfloat16 l1 = __float2bfloat16(a.y - __bfloat162float(h1));
    __nv_bfloat162 hh; hh.x = h0; hh.y = h1;
    __nv_bfloat162 ll; ll.x = l0; ll.y = l1;
    __nv_bfloat16* dst = g_wbf + (size_t)n * KE + k;
    *(__nv_bfloat162*)(dst)        = hh;
    *(__nv_bfloat162*)(dst + 1024) = hh;
    *(__nv_bfloat162*)(dst + 2048) = ll;
}

__global__ __launch_bounds__(256) void conv_h0_kernel(const float* __restrict__ h0)
{
    int i = blockIdx.x * 256 + threadIdx.x;     // 65536 elems
    float v = h0[i];
    __nv_bfloat16 h = __float2bfloat16(v);
    g_hh[0][i] = h;
    g_hl[0][i] = __float2bfloat16(v - __bfloat162float(h));
}

// ---------------------------------------------------------------------------
// mma.sync bf16 GEMM for x_proj (validated; 2 CTAs/SM) — unchanged
// ---------------------------------------------------------------------------
__global__ __launch_bounds__(256, 2) void gemm_mma(
    const float* __restrict__ b0, const float* __restrict__ b1,
    const float* __restrict__ b2, const float* __restrict__ b3)
{
    __shared__ __align__(128) char smA[2][8192];
    __shared__ __align__(128) char smB[2][8192];

    const int tid = threadIdx.x, wid = tid >> 5, lane = tid & 31;
    const int mTile = blockIdx.x >> 5, nTile = blockIdx.x & 31;
    const int m0 = mTile * 128, n0 = nTile * 128;
    const int m_w = (wid & 3) * 32;
    const int n_wb = (wid >> 2) * 64;

    const uint32_t sA = smem_u32(smA);
    const uint32_t sB = smem_u32(smB);

    const int r0i = tid >> 2, s0 = tid & 3;
    const int r1i = (tid + 256) >> 2, s1 = (tid + 256) & 3;
    const uint32_t st0 = (uint32_t)((r0i >> 1) * 128 + ((((r0i & 1) * 4 + s0) ^ ((r0i >> 1) & 7)) * 16));
    const uint32_t st1 = (uint32_t)((r1i >> 1) * 128 + ((((r1i & 1) * 4 + s1) ^ ((r1i >> 1) & 7)) * 16));
    const __nv_bfloat16* gA0 = g_abf + (size_t)(m0 + r0i) * KE + s0 * 8;
    const __nv_bfloat16* gA1 = g_abf + (size_t)(m0 + r1i) * KE + s1 * 8;
    const __nv_bfloat16* gB0 = g_wbf + (size_t)(n0 + r0i) * KE + s0 * 8;
    const __nv_bfloat16* gB1 = g_wbf + (size_t)(n0 + r1i) * KE + s1 * 8;

    const int row_l = lane & 15, sh = lane >> 4;
    uint32_t offA[2], offB[4];
    #pragma unroll
    for (int a = 0; a < 2; a++) {
        int r = m_w + a * 16 + row_l;
        int L = r >> 1, p = (r & 1) * 4 + sh;
        offA[a] = (uint32_t)(L * 128 + ((p ^ (L & 7)) * 16));
    }
    #pragma unroll
    for (int b = 0; b < 4; b++) {
        int r = n_wb + b * 16 + row_l;
        int L = r >> 1, p = (r & 1) * 4 + sh;
        offB[b] = (uint32_t)(L * 128 + ((p ^ (L & 7)) * 16));
    }

    float acc[2][8][4];
    #pragma unroll
    for (int a = 0; a < 2; a++)
        #pragma unroll
        for (int n = 0; n < 8; n++)
            #pragma unroll
            for (int c = 0; c < 4; c++) acc[a][n][c] = 0.0f;

    *(uint4*)(smA[0] + st0) = *(const uint4*)(gA0);
    *(uint4*)(smA[0] + st1) = *(const uint4*)(gA1);
    *(uint4*)(smB[0] + st0) = *(const uint4*)(gB0);
    *(uint4*)(smB[0] + st1) = *(const uint4*)(gB1);
    __syncthreads();

    int buf = 0;
    for (int ch = 0; ch < 96; ch++) {
        if (ch < 95) {
            const int nb = buf ^ 1;
            const int ko = (ch + 1) * 32;
            *(uint4*)(smA[nb] + st0) = *(const uint4*)(gA0 + ko);
            *(uint4*)(smA[nb] + st1) = *(const uint4*)(gA1 + ko);
            *(uint4*)(smB[nb] + st0) = *(const uint4*)(gB0 + ko);
            *(uint4*)(smB[nb] + st1) = *(const uint4*)(gB1 + ko);
        }
        const uint32_t bA = sA + buf * 8192;
        const uint32_t bB = sB + buf * 8192;
        #pragma unroll
        for (int ks = 0; ks < 2; ks++) {
            const uint32_t kx = ks * 32;
            uint32_t af[2][4], bf_[4][4];
            #pragma unroll
            for (int a = 0; a < 2; a++)
                LDMX4(af[a][0], af[a][1], af[a][2], af[a][3], (bA + offA[a]) ^ kx);
            #pragma unroll
            for (int b = 0; b < 4; b++)
                LDMX4(bf_[b][0], bf_[b][1], bf_[b][2], bf_[b][3], (bB + offB[b]) ^ kx);
            #pragma unroll
            for (int a = 0; a < 2; a++)
                #pragma unroll
                for (int nt = 0; nt < 8; nt++) {
                    const int bt = nt >> 1, hl = nt & 1;
                    MMA16816(acc[a][nt], af[a][0], af[a][1], af[a][2], af[a][3],
                             bf_[bt][hl], bf_[bt][hl + 2]);
                }
        }
        __syncthreads();
        buf ^= 1;
    }

    const int q = n0 >> 10;
    const float* bp = (q == 0) ? b0 : (q == 1) ? b1 : (q == 2) ? b2 : b3;
    const int nqb = (n0 & 1023) + n_wb;
    #pragma unroll
    for (int a = 0; a < 2; a++) {
        const int row0 = m0 + m_w + a * 16 + (lane >> 2);
        #pragma unroll
        for (int nt = 0; nt < 8; nt++) {
            const int col = n_wb + nt * 8 + (lane & 3) * 2;
            const float bv0 = __ldg(bp + nqb + nt * 8 + (lane & 3) * 2);
            const float bv1 = __ldg(bp + nqb + nt * 8 + (lane & 3) * 2 + 1);
            float2 v0 = make_float2(acc[a][nt][0] + bv0, acc[a][nt][1] + bv1);
            float2 v1 = make_float2(acc[a][nt][2] + bv0, acc[a][nt][3] + bv1);
            *(float2*)(g_xp + (size_t)row0 * G4 + n0 + col)       = v0;
            *(float2*)(g_xp + (size_t)(row0 + 8) * G4 + n0 + col) = v1;
        }
    }
}

// ===========================================================================
// Phase 2: persistent tensor-core scan. 128 CTAs x 512 thr.
// MMA warps 0-7: warp = (mq = wid&1: 32-batch half) x (s = wid>>1: k-quarter).
// Warp tile 32m x 32n for its k-slice: per k-step 8 LDMX4 -> 24 MMAs
// (0.33 loads/MMA, half of R14's crossbar traffic). All 3 split terms
// accumulate into one fp32 acc. K-partials -> gb[4] slices, summed at gates.
// Staging warps 8-15: h hi/lo LDG->STS (R15 validated mapping).
// ===========================================================================
#define SMS_WH 65536
#define SMS_HS 65536
#define GB_SL 2112                     // floats per gb slice (64*33)
#define SM_SCAN3 (2*SMS_WH + SMS_HS + 4*GB_SL*4)   // 230400

__global__ __launch_bounds__(512, 1) void lstm_scan_mma(
    const float* __restrict__ c0,
    const float* __restrict__ Whi, const float* __restrict__ Whf,
    const float* __restrict__ Whg, const float* __restrict__ Who,
    float* __restrict__ out)
{
    extern __shared__ char sm[];
    char* whh = sm;                      // Wh_hi: 32 k-subtiles x 2048 B
    char* whl = sm + SMS_WH;             // Wh_lo
    char* hs  = sm + 2 * SMS_WH;         // h stage: [2 buf][hi 16K | lo 16K]
    float* gb = (float*)(sm + 2 * SMS_WH + SMS_HS);   // [4][64][33]

    const int tid = threadIdx.x, wid = tid >> 5, lane = tid & 31;
    const int j0 = blockIdx.x * 8;

    // ---- one-time: Wh -> smem swizzled bf16 hi/lo (512 threads) ----
    const float* Wm[4] = {Whi, Whf, Whg, Who};
    {
        const int r = tid >> 4;          // 0..31
        const int kt = tid & 15;         // k window kt*64..+63
        const float* src = Wm[r >> 3] + (size_t)(j0 + (r & 7)) * Hh + kt * 64;
        const int L = r >> 1, rb4 = (r & 1) * 4, Lx = L & 7;
        for (int kk = 0; kk < 64; kk += 4) {
            const int k = kt * 64 + kk;
            float4 v = *(const float4*)(src + kk);
            union { __nv_bfloat16 b[4]; ull u; } uh, ul;
            #pragma unroll
            for (int e = 0; e < 4; e++) {
                float f = (&v.x)[e];
                uh.b[e] = __float2bfloat16(f);
                ul.b[e] = __float2bfloat16(f - __bfloat162float(uh.b[e]));
            }
            const int c = k >> 5, s = (k & 31) >> 3, e0 = k & 7;
            const int addr = c * 2048 + L * 128 + (((rb4 + s) ^ Lx) * 16) + e0 * 2;
            *(ull*)(whh + addr) = uh.u;
            *(ull*)(whl + addr) = ul.u;
        }
    }

    // MMA warps: mapping + ldmatrix offsets (validated formula)
    const int row_l = lane & 15, sh = lane >> 4;
    const int mq = wid & 1;              // m half (batches mq*32..+31)
    const int ksl = wid >> 1;            // k-slice 0..3 (MMA warps only)
    uint32_t offA0, offA1, offB0, offB1;
    {
        int r = mq * 32 + row_l;
        int L = r >> 1, p = (r & 1) * 4 + sh;
        offA0 = (uint32_t)(L * 128 + ((p ^ (L & 7)) * 16));
        r = mq * 32 + 16 + row_l;
        L = r >> 1; p = (r & 1) * 4 + sh;
        offA1 = (uint32_t)(L * 128 + ((p ^ (L & 7)) * 16));
        r = row_l;
        L = r >> 1; p = (r & 1) * 4 + sh;
        offB0 = (uint32_t)(L * 128 + ((p ^ (L & 7)) * 16));
        r = 16 + row_l;
        L = r >> 1; p = (r & 1) * 4 + sh;
        offB1 = (uint32_t)(L * 128 + ((p ^ (L & 7)) * 16));
    }
    const uint32_t hsu = smem_u32(hs);
    const uint32_t whhu = smem_u32(whh);
    const uint32_t whlu = smem_u32(whl);

    // staging warps (wid>=8): thread stid 0..255 -> (batch sb, 16B seg ss)
    const int stid = tid - 256;
    const int sb = (stid >= 0) ? (stid >> 2) : 0, ss = (stid >= 0) ? (stid & 3) : 0;
    const uint32_t stg = (uint32_t)((sb >> 1) * 128 + ((((sb & 1) * 4 + ss) ^ ((sb >> 1) & 7)) * 16));
    const size_t gsb = (size_t)sb * Hh + ss * 8;

    // gate cells: 1 per thread (512 cells)
    const int grb = tid >> 3, grj = tid & 7;
    float creg = c0[grb * Hh + j0 + grj];
    __syncthreads();

    for (int t = 0; t < Tt; t++) {
        const int cur = t & 1, nxt = cur ^ 1;
        const __nv_bfloat16* hhp = g_hh[cur];
        const __nv_bfloat16* hlp = g_hl[cur];

        // prefetch x_proj contribution for this thread's cell
        float xq0, xq1, xq2, xq3;
        {
            const float* xb = g_xp + ((size_t)grb * Tt + t) * G4 + j0 + grj;
            xq0 = xb[0]; xq1 = xb[Hh]; xq2 = xb[2 * Hh]; xq3 = xb[3 * Hh];
        }

        float acc[2][4][4];                  // [m-block][n8][regs]
        #pragma unroll
        for (int mb = 0; mb < 2; mb++)
            #pragma unroll
            for (int n8 = 0; n8 < 4; n8++)
                #pragma unroll
                for (int c = 0; c < 4; c++) acc[mb][n8][c] = 0.0f;

        // stage chunk 0 (staging warps only)
        if (wid >= 8) {
            #pragma unroll
            for (int sc = 0; sc < 4; sc++) {
                *(uint4*)(hs + sc * 4096 + stg)         = *(const uint4*)(hhp + gsb + sc * 32);
                *(uint4*)(hs + 16384 + sc * 4096 + stg) = *(const uint4*)(hlp + gsb + sc * 32);
            }
        }
        __syncthreads();

        int buf = 0;
        for (int ch = 0; ch < 8; ch++) {
            if (wid >= 8) {                  // staging warps: next chunk
                if (ch < 7) {
                    const int nb = buf ^ 1;
                    #pragma unroll
                    for (int sc = 0; sc < 4; sc++) {
                        uint4 ph = *(const uint4*)(hhp + gsb + (ch + 1) * 128 + sc * 32);
                        uint4 pl = *(const uint4*)(hlp + gsb + (ch + 1) * 128 + sc * 32);
                        *(uint4*)(hs + nb * 32768 + sc * 4096 + stg)         = ph;
                        *(uint4*)(hs + nb * 32768 + 16384 + sc * 4096 + stg) = pl;
                    }
                }
            } else {                         // MMA warps: sub-tile ksl of chunk
                const uint32_t wHc = whhu + (ch * 4 + ksl) * 2048;
                const uint32_t wLc = whlu + (ch * 4 + ksl) * 2048;
                const uint32_t aHi = hsu + buf * 32768 + ksl * 4096;
                const uint32_t aLo = aHi + 16384;
                #pragma unroll
                for (int ks = 0; ks < 2; ks++) {
                    const uint32_t kx = ks * 32;
                    uint32_t ah0[4], ah1[4], al0[4], al1[4], bh[4], bl[4];
                    LDMX4(ah0[0], ah0[1], ah0[2], ah0[3], (aHi + offA0) ^ kx);
                    LDMX4(ah1[0], ah1[1], ah1[2], ah1[3], (aHi + offA1) ^ kx);
                    LDMX4(al0[0], al0[1], al0[2], al0[3], (aLo + offA0) ^ kx);
                    LDMX4(al1[0], al1[1], al1[2], al1[3], (aLo + offA1) ^ kx);
                    // n8 blocks 0,1 (B rows 0-15)
                    LDMX4(bh[0], bh[1], bh[2], bh[3], (wHc + offB0) ^ kx);
                    LDMX4(bl[0], bl[1], bl[2], bl[3], (wLc + offB0) ^ kx);
                    #pragma unroll
                    for (int n8 = 0; n8 < 2; n8++) {
                        MMA16816(acc[0][n8], ah0[0], ah0[1], ah0[2], ah0[3], bh[n8], bh[n8 + 2]);
                        MMA16816(acc[0][n8], al0[0], al0[1], al0[2], al0[3], bh[n8], bh[n8 + 2]);
                        MMA16816(acc[0][n8], ah0[0], ah0[1], ah0[2], ah0[3], bl[n8], bl[n8 + 2]);
                        MMA16816(acc[1][n8], ah1[0], ah1[1], ah1[2], ah1[3], bh[n8], bh[n8 + 2]);
                        MMA16816(acc[1][n8], al1[0], al1[1], al1[2], al1[3], bh[n8], bh[n8 + 2]);
                        MMA16816(acc[1][n8], ah1[0], ah1[1], ah1[2], ah1[3], bl[n8], bl[n8 + 2]);
                    }
                    // n8 blocks 2,3 (B rows 16-31)
                    LDMX4(bh[0], bh[1], bh[2], bh[3], (wHc + offB1) ^ kx);
                    LDMX4(bl[0], bl[1], bl[2], bl[3], (wLc + offB1) ^ kx);
                    #pragma unroll
                    for (int n8 = 0; n8 < 2; n8++) {
                        MMA16816(acc[0][n8 + 2], ah0[0], ah0[1], ah0[2], ah0[3], bh[n8], bh[n8 + 2]);
                        MMA16816(acc[0][n8 + 2], al0[0], al0[1], al0[2], al0[3], bh[n8], bh[n8 + 2]);
                        MMA16816(acc[0][n8 + 2], ah0[0], ah0[1], ah0[2], ah0[3], bl[n8], bl[n8 + 2]);
                        MMA16816(acc[1][n8 + 2], ah1[0], ah1[1], ah1[2], ah1[3], bh[n8], bh[n8 + 2]);
                        MMA16816(acc[1][n8 + 2], al1[0], al1[1], al1[2], al1[3], bh[n8], bh[n8 + 2]);
                        MMA16816(acc[1][n8 + 2], ah1[0], ah1[1], ah1[2], ah1[3], bl[n8], bl[n8 + 2]);
                    }
                }
            }
            __syncthreads();
            buf ^= 1;
        }

        // MMA warps write k-partials into gb slice ksl
        if (wid < 8) {
            float* base = gb + ksl * GB_SL;
            #pragma unroll
            for (int mb = 0; mb < 2; mb++) {
                const int erow = mq * 32 + mb * 16 + (lane >> 2);
                #pragma unroll
                for (int n8 = 0; n8 < 4; n8++) {
                    const int ecol = n8 * 8 + (lane & 3) * 2;
                    float* q0 = base + erow * 33 + ecol;
                    q0[0] = acc[mb][n8][0]; q0[1] = acc[mb][n8][1];
                    float* q1 = base + (erow + 8) * 33 + ecol;
                    q1[0] = acc[mb][n8][2]; q1[1] = acc[mb][n8][3];
                }
            }
        }
        __syncthreads();

        // gates: sum 4 k-slices + x_proj; state update + h hi/lo store
        {
            const int go_ = grb * 33 + grj;
            float gi = gb[go_]              + gb[GB_SL + go_]
                     + gb[2 * GB_SL + go_]  + gb[3 * GB_SL + go_] + xq0;
            float gf = gb[go_ + 8]          + gb[GB_SL + go_ + 8]
                     + gb[2 * GB_SL + go_ + 8] + gb[3 * GB_SL + go_ + 8] + xq1;
            float gg = gb[go_ + 16]         + gb[GB_SL + go_ + 16]
                     + gb[2 * GB_SL + go_ + 16] + gb[3 * GB_SL + go_ + 16] + xq2;
            float gov = gb[go_ + 24]        + gb[GB_SL + go_ + 24]
                     + gb[2 * GB_SL + go_ + 24] + gb[3 * GB_SL + go_ + 24] + xq3;
            float iv = sigf(gi), fv = sigf(gf), ov = sigf(gov);
            float gv = 2.0f * sigf(2.0f * gg) - 1.0f;
            creg = fv * creg + iv * gv;
            float hv = ov * (2.0f * sigf(2.0f * creg) - 1.0f);
            const size_t hidx = (size_t)grb * Hh + j0 + grj;
            __nv_bfloat16 hb_ = __float2bfloat16(hv);
            g_hh[nxt][hidx] = hb_;
            g_hl[nxt][hidx] = __float2bfloat16(hv - __bfloat162float(hb_));
            out[((size_t)grb * Tt + t) * Hh + j0 + grj] = hv;
            if (t == Tt - 1) {
                out[HSEQ_N + hidx] = hv;
                out[HSEQ_N + Bb * Hh + hidx] = creg;
            }
        }

        if (t < Tt - 1) {                    // grid barrier
            __syncthreads();
            if (tid == 0) {
                __threadfence();
                unsigned g = *(volatile unsigned*)&g_bar_gen;
                if (atomicAdd(&g_bar_count, 1u) == gridDim.x - 1u) {
                    atomicExch(&g_bar_count, 0u);
                    __threadfence();
                    atomicAdd(&g_bar_gen, 1u);
                } else {
                    while (*(volatile unsigned*)&g_bar_gen == g) __nanosleep(64);
                }
                __threadfence();
            }
            __syncthreads();
        }
    }
}

// ===========================================================================
extern "C" void kernel_launch(void* const* d_in, const int* in_sizes, int n_in,
                              void* d_out, int out_size)
{
    (void)in_sizes; (void)n_in; (void)out_size;
    const float* x   = (const float*)d_in[0];
    const float* h0  = (const float*)d_in[1];
    const float* c0  = (const float*)d_in[2];
    const float* Wii = (const float*)d_in[3];
    const float* Whi = (const float*)d_in[4];
    const float* bi  = (const float*)d_in[5];
    const float* Wif = (const float*)d_in[6];
    const float* Whf = (const float*)d_in[7];
    const float* bf  = (const float*)d_in[8];
    const float* Wig = (const float*)d_in[9];
    const float* Whg = (const float*)d_in[10];
    const float* bg_ = (const float*)d_in[11];
    const float* Wio = (const float*)d_in[12];
    const float* Who = (const float*)d_in[13];
    const float* bo  = (const float*)d_in[14];
    float* out = (float*)d_out;

    conv_a_kernel<<<65536, 256>>>(x);                   // A' bf16 split
    conv_w_kernel<<<8192, 256>>>(Wii, Wif, Wig, Wio);   // W' bf16 split
    conv_h0_kernel<<<256, 256>>>(h0);                   // h0 hi/lo
    gemm_mma<<<8192, 256>>>(bi, bf, bg_, bo);           // x_proj via HMMA

    static int attr_done = 0;
    if (!attr_done) {
        cudaFuncSetAttribute(lstm_scan_mma,
                             cudaFuncAttributeMaxDynamicSharedMemorySize, SM_SCAN3);
        attr_done = 1;
    }
    lstm_scan_mma<<<128, 512, SM_SCAN3>>>(c0, Whi, Whf, Whg, Who, out);
}

// round 17
// speedup vs baseline: 1.2110x; 1.1658x over previous
#include <cuda_runtime.h>
#include <cuda_bf16.h>
#include <cuda_fp16.h>
#include <cstdint>

typedef unsigned long long ull;
union F2 { float2 f; ull u; };

#define Bb 64
#define Tt 512
#define Hh 1024
#define G4 4096
#define KE 3072
#define HSEQ_N (Bb*Tt*Hh)

// scratch (device globals: allocation-free rule)
__device__ float g_xp[(size_t)Bb * Tt * G4];          // 512 MB x_proj
__device__ __nv_bfloat16 g_abf[(size_t)Bb * Tt * KE]; // 192 MB  A' = [hi, lo, hi]
__device__ __nv_bfloat16 g_wbf[(size_t)G4 * KE];      // 24 MB   W' = [hi, hi, lo]
__device__ __half g_hh[2][Bb * Hh];                   // h fp16 hi, double-buffered
__device__ __half g_hl[2][Bb * Hh];                   // h fp16 lo
__device__ unsigned g_bar_count;
__device__ unsigned g_bar_gen;

__device__ __forceinline__ uint32_t smem_u32(const void* p) {
    uint32_t a;
    asm("{ .reg .u64 t; cvta.to.shared.u64 t, %1; cvt.u32.u64 %0, t; }" : "=r"(a) : "l"(p));
    return a;
}

#define LDMX4(r0,r1,r2,r3,addr) \
    asm volatile("ldmatrix.sync.aligned.m8n8.x4.shared.b16 {%0,%1,%2,%3}, [%4];" \
        : "=r"(r0), "=r"(r1), "=r"(r2), "=r"(r3) : "r"(addr))

#define MMA16816(d,a0,a1,a2,a3,b0,b1) \
    asm volatile("mma.sync.aligned.m16n8k16.row.col.f32.bf16.bf16.f32 " \
        "{%0,%1,%2,%3}, {%4,%5,%6,%7}, {%8,%9}, {%0,%1,%2,%3};" \
        : "+f"((d)[0]), "+f"((d)[1]), "+f"((d)[2]), "+f"((d)[3]) \
        : "r"(a0), "r"(a1), "r"(a2), "r"(a3), "r"(b0), "r"(b1))

#define MMA16816H(d,a0,a1,a2,a3,b0,b1) \
    asm volatile("mma.sync.aligned.m16n8k16.row.col.f32.f16.f16.f32 " \
        "{%0,%1,%2,%3}, {%4,%5,%6,%7}, {%8,%9}, {%0,%1,%2,%3};" \
        : "+f"((d)[0]), "+f"((d)[1]), "+f"((d)[2]), "+f"((d)[3]) \
        : "r"(a0), "r"(a1), "r"(a2), "r"(a3), "r"(b0), "r"(b1))

__device__ __forceinline__ float sigf(float x) { return 1.0f / (1.0f + __expf(-x)); }

// ---------------------------------------------------------------------------
// bf16-split conversions (xproj path, unchanged / validated)
// ---------------------------------------------------------------------------
__global__ __launch_bounds__(256) void conv_a_kernel(const float* __restrict__ x)
{
    size_t base = ((size_t)blockIdx.x * 256 + threadIdx.x) * 2;
    int m = (int)(base >> 10), k = (int)(base & 1023);
    float2 a = *(const float2*)(x + base);
    __nv_bfloat16 h0 = __float2bfloat16(a.x);
    __nv_bfloat16 h1 = __float2bfloat16(a.y);
    __nv_bfloat16 l0 = __float2bfloat16(a.x - __bfloat162float(h0));
    __nv_bfloat16 l1 = __float2bfloat16(a.y - __bfloat162float(h1));
    __nv_bfloat162 hh; hh.x = h0; hh.y = h1;
    __nv_bfloat162 ll; ll.x = l0; ll.y = l1;
    __nv_bfloat16* dst = g_abf + (size_t)m * KE + k;
    *(__nv_bfloat162*)(dst)        = hh;
    *(__nv_bfloat162*)(dst + 1024) = ll;
    *(__nv_bfloat162*)(dst + 2048) = hh;
}

__global__ __launch_bounds__(256) void conv_w_kernel(
    const float* __restrict__ W0, const float* __restrict__ W1,
    const float* __restrict__ W2, const float* __restrict__ W3)
{
    size_t base = ((size_t)blockIdx.x * 256 + threadIdx.x) * 2;
    int n = (int)(base >> 10), k = (int)(base & 1023);
    int q = n >> 10;
    const float* W = (q == 0) ? W0 : (q == 1) ? W1 : (q == 2) ? W2 : W3;
    float2 a = *(const float2*)(W + (size_t)(n & 1023) * 1024 + k);
    __nv_bfloat16 h0 = __float2bfloat16(a.x);
    __nv_bfloat16 h1 = __float2bfloat16(a.y);
    __nv_bfloat16 l0 = __float2bfloat16(a.x - __bfloat162float(h0));
    __nv_bfloat16 l1 = __float2bfloat16(a.y - __bfloat162float(h1));
    __nv_bfloat162 hh; hh.x = h0; hh.y = h1;
    __nv_bfloat162 ll; ll.x = l0; ll.y = l1;
    __nv_bfloat16* dst = g_wbf + (size_t)n * KE + k;
    *(__nv_bfloat162*)(dst)        = hh;
    *(__nv_bfloat162*)(dst + 1024) = hh;
    *(__nv_bfloat162*)(dst + 2048) = ll;
}

__global__ __launch_bounds__(256) void conv_h0_kernel(const float* __restrict__ h0)
{
    int i = blockIdx.x * 256 + threadIdx.x;     // 65536 elems
    float v = h0[i];
    __half h = __float2half(v);
    g_hh[0][i] = h;
    g_hl[0][i] = __float2half(v - __half2float(h));
}

// ---------------------------------------------------------------------------
// mma.sync bf16 GEMM for x_proj (validated; 2 CTAs/SM) — unchanged
// ---------------------------------------------------------------------------
__global__ __launch_bounds__(256, 2) void gemm_mma(
    const float* __restrict__ b0, const float* __restrict__ b1,
    const float* __restrict__ b2, const float* __restrict__ b3)
{
    __shared__ __align__(128) char smA[2][8192];
    __shared__ __align__(128) char smB[2][8192];

    const int tid = threadIdx.x, wid = tid >> 5, lane = tid & 31;
    const int mTile = blockIdx.x >> 5, nTile = blockIdx.x & 31;
    const int m0 = mTile * 128, n0 = nTile * 128;
    const int m_w = (wid & 3) * 32;
    const int n_wb = (wid >> 2) * 64;

    const uint32_t sA = smem_u32(smA);
    const uint32_t sB = smem_u32(smB);

    const int r0i = tid >> 2, s0 = tid & 3;
    const int r1i = (tid + 256) >> 2, s1 = (tid + 256) & 3;
    const uint32_t st0 = (uint32_t)((r0i >> 1) * 128 + ((((r0i & 1) * 4 + s0) ^ ((r0i >> 1) & 7)) * 16));
    const uint32_t st1 = (uint32_t)((r1i >> 1) * 128 + ((((r1i & 1) * 4 + s1) ^ ((r1i >> 1) & 7)) * 16));
    const __nv_bfloat16* gA0 = g_abf + (size_t)(m0 + r0i) * KE + s0 * 8;
    const __nv_bfloat16* gA1 = g_abf + (size_t)(m0 + r1i) * KE + s1 * 8;
    const __nv_bfloat16* gB0 = g_wbf + (size_t)(n0 + r0i) * KE + s0 * 8;
    const __nv_bfloat16* gB1 = g_wbf + (size_t)(n0 + r1i) * KE + s1 * 8;

    const int row_l = lane & 15, sh = lane >> 4;
    uint32_t offA[2], offB[4];
    #pragma unroll
    for (int a = 0; a < 2; a++) {
        int r = m_w + a * 16 + row_l;
        int L = r >> 1, p = (r & 1) * 4 + sh;
        offA[a] = (uint32_t)(L * 128 + ((p ^ (L & 7)) * 16));
    }
    #pragma unroll
    for (int b = 0; b < 4; b++) {
        int r = n_wb + b * 16 + row_l;
        int L = r >> 1, p = (r & 1) * 4 + sh;
        offB[b] = (uint32_t)(L * 128 + ((p ^ (L & 7)) * 16));
    }

    float acc[2][8][4];
    #pragma unroll
    for (int a = 0; a < 2; a++)
        #pragma unroll
        for (int n = 0; n < 8; n++)
            #pragma unroll
            for (int c = 0; c < 4; c++) acc[a][n][c] = 0.0f;

    *(uint4*)(smA[0] + st0) = *(const uint4*)(gA0);
    *(uint4*)(smA[0] + st1) = *(const uint4*)(gA1);
    *(uint4*)(smB[0] + st0) = *(const uint4*)(gB0);
    *(uint4*)(smB[0] + st1) = *(const uint4*)(gB1);
    __syncthreads();

    int buf = 0;
    for (int ch = 0; ch < 96; ch++) {
        if (ch < 95) {
            const int nb = buf ^ 1;
            const int ko = (ch + 1) * 32;
            *(uint4*)(smA[nb] + st0) = *(const uint4*)(gA0 + ko);
            *(uint4*)(smA[nb] + st1) = *(const uint4*)(gA1 + ko);
            *(uint4*)(smB[nb] + st0) = *(const uint4*)(gB0 + ko);
            *(uint4*)(smB[nb] + st1) = *(const uint4*)(gB1 + ko);
        }
        const uint32_t bA = sA + buf * 8192;
        const uint32_t bB = sB + buf * 8192;
        #pragma unroll
        for (int ks = 0; ks < 2; ks++) {
            const uint32_t kx = ks * 32;
            uint32_t af[2][4], bf_[4][4];
            #pragma unroll
            for (int a = 0; a < 2; a++)
                LDMX4(af[a][0], af[a][1], af[a][2], af[a][3], (bA + offA[a]) ^ kx);
            #pragma unroll
            for (int b = 0; b < 4; b++)
                LDMX4(bf_[b][0], bf_[b][1], bf_[b][2], bf_[b][3], (bB + offB[b]) ^ kx);
            #pragma unroll
            for (int a = 0; a < 2; a++)
                #pragma unroll
                for (int nt = 0; nt < 8; nt++) {
                    const int bt = nt >> 1, hl = nt & 1;
                    MMA16816(acc[a][nt], af[a][0], af[a][1], af[a][2], af[a][3],
                             bf_[bt][hl], bf_[bt][hl + 2]);
                }
        }
        __syncthreads();
        buf ^= 1;
    }

    const int q = n0 >> 10;
    const float* bp = (q == 0) ? b0 : (q == 1) ? b1 : (q == 2) ? b2 : b3;
    const int nqb = (n0 & 1023) + n_wb;
    #pragma unroll
    for (int a = 0; a < 2; a++) {
        const int row0 = m0 + m_w + a * 16 + (lane >> 2);
        #pragma unroll
        for (int nt = 0; nt < 8; nt++) {
            const int col = n_wb + nt * 8 + (lane & 3) * 2;
            const float bv0 = __ldg(bp + nqb + nt * 8 + (lane & 3) * 2);
            const float bv1 = __ldg(bp + nqb + nt * 8 + (lane & 3) * 2 + 1);
            float2 v0 = make_float2(acc[a][nt][0] + bv0, acc[a][nt][1] + bv1);
            float2 v1 = make_float2(acc[a][nt][2] + bv0, acc[a][nt][3] + bv1);
            *(float2*)(g_xp + (size_t)row0 * G4 + n0 + col)       = v0;
            *(float2*)(g_xp + (size_t)(row0 + 8) * G4 + n0 + col) = v1;
        }
    }
}

// ===========================================================================
// Phase 2: persistent tensor-core scan — 2-TERM FP16. 128 CTAs x 512 thr.
// gates = (h16 + hl16) @ W16   (dropped h@Wl term ~2^-11 of W)
// MMA warps 0-7: (mq = wid&1) x (ksl = wid>>1); warp tile 32m x 32n per
// k-quarter; per k-step 6 LDMX4 -> 16 MMAs. Staging warps 8-15: h hi/lo.
// Wh fp16 hi only in SMEM (64 KB). K-partials -> gb[4] slices.
// ===========================================================================
#define SMS_WH 65536
#define SMS_HS 65536
#define GB_SL 2112                     // floats per gb slice (64*33)
#define SM_SCAN3 (SMS_WH + SMS_HS + 4*GB_SL*4)   // 164864

__global__ __launch_bounds__(512, 1) void lstm_scan_mma(
    const float* __restrict__ c0,
    const float* __restrict__ Whi, const float* __restrict__ Whf,
    const float* __restrict__ Whg, const float* __restrict__ Who,
    float* __restrict__ out)
{
    extern __shared__ char sm[];
    char* whh = sm;                      // Wh fp16: 32 k-subtiles x 2048 B
    char* hs  = sm + SMS_WH;             // h stage: [2 buf][hi 16K | lo 16K]
    float* gb = (float*)(sm + SMS_WH + SMS_HS);   // [4][64][33]

    const int tid = threadIdx.x, wid = tid >> 5, lane = tid & 31;
    const int j0 = blockIdx.x * 8;

    // ---- one-time: Wh -> smem swizzled fp16 (512 threads) ----
    const float* Wm[4] = {Whi, Whf, Whg, Who};
    {
        const int r = tid >> 4;          // 0..31
        const int kt = tid & 15;         // k window kt*64..+63
        const float* src = Wm[r >> 3] + (size_t)(j0 + (r & 7)) * Hh + kt * 64;
        const int L = r >> 1, rb4 = (r & 1) * 4, Lx = L & 7;
        for (int kk = 0; kk < 64; kk += 4) {
            const int k = kt * 64 + kk;
            float4 v = *(const float4*)(src + kk);
            union { __half b[4]; ull u; } uh;
            #pragma unroll
            for (int e = 0; e < 4; e++)
                uh.b[e] = __float2half((&v.x)[e]);
            const int c = k >> 5, s = (k & 31) >> 3, e0 = k & 7;
            const int addr = c * 2048 + L * 128 + (((rb4 + s) ^ Lx) * 16) + e0 * 2;
            *(ull*)(whh + addr) = uh.u;
        }
    }

    // MMA warps: mapping + ldmatrix offsets (validated formula)
    const int row_l = lane & 15, sh = lane >> 4;
    const int mq = wid & 1;              // m half (batches mq*32..+31)
    const int ksl = wid >> 1;            // k-slice 0..3 (MMA warps only)
    uint32_t offA0, offA1, offB0, offB1;
    {
        int r = mq * 32 + row_l;
        int L = r >> 1, p = (r & 1) * 4 + sh;
        offA0 = (uint32_t)(L * 128 + ((p ^ (L & 7)) * 16));
        r = mq * 32 + 16 + row_l;
        L = r >> 1; p = (r & 1) * 4 + sh;
        offA1 = (uint32_t)(L * 128 + ((p ^ (L & 7)) * 16));
        r = row_l;
        L = r >> 1; p = (r & 1) * 4 + sh;
        offB0 = (uint32_t)(L * 128 + ((p ^ (L & 7)) * 16));
        r = 16 + row_l;
        L = r >> 1; p = (r & 1) * 4 + sh;
        offB1 = (uint32_t)(L * 128 + ((p ^ (L & 7)) * 16));
    }
    const uint32_t hsu = smem_u32(hs);
    const uint32_t whhu = smem_u32(whh);

    // staging warps (wid>=8): thread stid 0..255 -> (batch sb, 16B seg ss)
    const int stid = tid - 256;
    const int sb = (stid >= 0) ? (stid >> 2) : 0, ss = (stid >= 0) ? (stid & 3) : 0;
    const uint32_t stg = (uint32_t)((sb >> 1) * 128 + ((((sb & 1) * 4 + ss) ^ ((sb >> 1) & 7)) * 16));
    const size_t gsb = (size_t)sb * Hh + ss * 8;

    // gate cells: 1 per thread (512 cells)
    const int grb = tid >> 3, grj = tid & 7;
    float creg = c0[grb * Hh + j0 + grj];
    __syncthreads();

    for (int t = 0; t < Tt; t++) {
        const int cur = t & 1, nxt = cur ^ 1;
        const __half* hhp = g_hh[cur];
        const __half* hlp = g_hl[cur];

        // prefetch x_proj contribution for this thread's cell
        float xq0, xq1, xq2, xq3;
        {
            const float* xb = g_xp + ((size_t)grb * Tt + t) * G4 + j0 + grj;
            xq0 = xb[0]; xq1 = xb[Hh]; xq2 = xb[2 * Hh]; xq3 = xb[3 * Hh];
        }

        float acc[2][4][4];                  // [m-block][n8][regs]
        #pragma unroll
        for (int mb = 0; mb < 2; mb++)
            #pragma unroll
            for (int n8 = 0; n8 < 4; n8++)
                #pragma unroll
                for (int c = 0; c < 4; c++) acc[mb][n8][c] = 0.0f;

        // stage chunk 0 (staging warps only)
        if (wid >= 8) {
            #pragma unroll
            for (int sc = 0; sc < 4; sc++) {
                *(uint4*)(hs + sc * 4096 + stg)         = *(const uint4*)(hhp + gsb + sc * 32);
                *(uint4*)(hs + 16384 + sc * 4096 + stg) = *(const uint4*)(hlp + gsb + sc * 32);
            }
        }
        __syncthreads();

        int buf = 0;
        for (int ch = 0; ch < 8; ch++) {
            if (wid >= 8) {                  // staging warps: next chunk
                if (ch < 7) {
                    const int nb = buf ^ 1;
                    #pragma unroll
                    for (int sc = 0; sc < 4; sc++) {
                        uint4 ph = *(const uint4*)(hhp + gsb + (ch + 1) * 128 + sc * 32);
                        uint4 pl = *(const uint4*)(hlp + gsb + (ch + 1) * 128 + sc * 32);
                        *(uint4*)(hs + nb * 32768 + sc * 4096 + stg)         = ph;
                        *(uint4*)(hs + nb * 32768 + 16384 + sc * 4096 + stg) = pl;
                    }
                }
            } else {                         // MMA warps: sub-tile ksl of chunk
                const uint32_t wHc = whhu + (ch * 4 + ksl) * 2048;
                const uint32_t aHi = hsu + buf * 32768 + ksl * 4096;
                const uint32_t aLo = aHi + 16384;
                #pragma unroll
                for (int ks = 0; ks < 2; ks++) {
                    const uint32_t kx = ks * 32;
                    uint32_t ah0[4], ah1[4], al0[4], al1[4], bh[4];
                    LDMX4(ah0[0], ah0[1], ah0[2], ah0[3], (aHi + offA0) ^ kx);
                    LDMX4(ah1[0], ah1[1], ah1[2], ah1[3], (aHi + offA1) ^ kx);
                    LDMX4(al0[0], al0[1], al0[2], al0[3], (aLo + offA0) ^ kx);
                    LDMX4(al1[0], al1[1], al1[2], al1[3], (aLo + offA1) ^ kx);
                    // n8 blocks 0,1 (B rows 0-15)
                    LDMX4(bh[0], bh[1], bh[2], bh[3], (wHc + offB0) ^ kx);
                    #pragma unroll
                    for (int n8 = 0; n8 < 2; n8++) {
                        MMA16816H(acc[0][n8], ah0[0], ah0[1], ah0[2], ah0[3], bh[n8], bh[n8 + 2]);
                        MMA16816H(acc[0][n8], al0[0], al0[1], al0[2], al0[3], bh[n8], bh[n8 + 2]);
                        MMA16816H(acc[1][n8], ah1[0], ah1[1], ah1[2], ah1[3], bh[n8], bh[n8 + 2]);
                        MMA16816H(acc[1][n8], al1[0], al1[1], al1[2], al1[3], bh[n8], bh[n8 + 2]);
                    }
                    // n8 blocks 2,3 (B rows 16-31)
                    LDMX4(bh[0], bh[1], bh[2], bh[3], (wHc + offB1) ^ kx);
                    #pragma unroll
                    for (int n8 = 0; n8 < 2; n8++) {
                        MMA16816H(acc[0][n8 + 2], ah0[0], ah0[1], ah0[2], ah0[3], bh[n8], bh[n8 + 2]);
                        MMA16816H(acc[0][n8 + 2], al0[0], al0[1], al0[2], al0[3], bh[n8], bh[n8 + 2]);
                        MMA16816H(acc[1][n8 + 2], ah1[0], ah1[1], ah1[2], ah1[3], bh[n8], bh[n8 + 2]);
                        MMA16816H(acc[1][n8 + 2], al1[0], al1[1], al1[2], al1[3], bh[n8], bh[n8 + 2]);
                    }
                }
            }
            __syncthreads();
            buf ^= 1;
        }

        // MMA warps write k-partials into gb slice ksl
        if (wid < 8) {
            float* base = gb + ksl * GB_SL;
            #pragma unroll
            for (int mb = 0; mb < 2; mb++) {
                const int erow = mq * 32 + mb * 16 + (lane >> 2);
                #pragma unroll
                for (int n8 = 0; n8 < 4; n8++) {
                    const int ecol = n8 * 8 + (lane & 3) * 2;
                    float* q0 = base + erow * 33 + ecol;
                    q0[0] = acc[mb][n8][0]; q0[1] = acc[mb][n8][1];
                    float* q1 = base + (erow + 8) * 33 + ecol;
                    q1[0] = acc[mb][n8][2]; q1[1] = acc[mb][n8][3];
                }
            }
        }
        __syncthreads();

        // gates: sum 4 k-slices + x_proj; state update + h fp16 hi/lo store
        {
            const int go_ = grb * 33 + grj;
            float gi = gb[go_]              + gb[GB_SL + go_]
                     + gb[2 * GB_SL + go_]  + gb[3 * GB_SL + go_] + xq0;
            float gf = gb[go_ + 8]          + gb[GB_SL + go_ + 8]
                     + gb[2 * GB_SL + go_ + 8] + gb[3 * GB_SL + go_ + 8] + xq1;
            float gg = gb[go_ + 16]         + gb[GB_SL + go_ + 16]
                     + gb[2 * GB_SL + go_ + 16] + gb[3 * GB_SL + go_ + 16] + xq2;
            float gov = gb[go_ + 24]        + gb[GB_SL + go_ + 24]
                     + gb[2 * GB_SL + go_ + 24] + gb[3 * GB_SL + go_ + 24] + xq3;
            float iv = sigf(gi), fv = sigf(gf), ov = sigf(gov);
            float gv = 2.0f * sigf(2.0f * gg) - 1.0f;
            creg = fv * creg + iv * gv;
            float hv = ov * (2.0f * sigf(2.0f * creg) - 1.0f);
            const size_t hidx = (size_t)grb * Hh + j0 + grj;
            __half h16 = __float2half(hv);
            g_hh[nxt][hidx] = h16;
            g_hl[nxt][hidx] = __float2half(hv - __half2float(h16));
            out[((size_t)grb * Tt + t) * Hh + j0 + grj] = hv;
            if (t == Tt - 1) {
                out[HSEQ_N + hidx] = hv;
                out[HSEQ_N + Bb * Hh + hidx] = creg;
            }
        }

        if (t < Tt - 1) {                    // grid barrier
            __syncthreads();
            if (tid == 0) {
                __threadfence();
                unsigned g = *(volatile unsigned*)&g_bar_gen;
                if (atomicAdd(&g_bar_count, 1u) == gridDim.x - 1u) {
                    atomicExch(&g_bar_count, 0u);
                    __threadfence();
                    atomicAdd(&g_bar_gen, 1u);
                } else {
                    while (*(volatile unsigned*)&g_bar_gen == g) __nanosleep(64);
                }
                __threadfence();
            }
            __syncthreads();
        }
    }
}

// ===========================================================================
extern "C" void kernel_launch(void* const* d_in, const int* in_sizes, int n_in,
                              void* d_out, int out_size)
{
    (void)in_sizes; (void)n_in; (void)out_size;
    const float* x   = (const float*)d_in[0];
    const float* h0  = (const float*)d_in[1];
    const float* c0  = (const float*)d_in[2];
    const float* Wii = (const float*)d_in[3];
    const float* Whi = (const float*)d_in[4];
    const float* bi  = (const float*)d_in[5];
    const float* Wif = (const float*)d_in[6];
    const float* Whf = (const float*)d_in[7];
    const float* bf  = (const float*)d_in[8];
    const float* Wig = (const float*)d_in[9];
    const float* Whg = (const float*)d_in[10];
    const float* bg_ = (const float*)d_in[11];
    const float* Wio = (const float*)d_in[12];
    const float* Who = (const float*)d_in[13];
    const float* bo  = (const float*)d_in[14];
    float* out = (float*)d_out;

    conv_a_kernel<<<65536, 256>>>(x);                   // A' bf16 split
    conv_w_kernel<<<8192, 256>>>(Wii, Wif, Wig, Wio);   // W' bf16 split
    conv_h0_kernel<<<256, 256>>>(h0);                   // h0 fp16 hi/lo
    gemm_mma<<<8192, 256>>>(bi, bf, bg_, bo);           // x_proj via HMMA

    static int attr_done = 0;
    if (!attr_done) {
        cudaFuncSetAttribute(lstm_scan_mma,
                             cudaFuncAttributeMaxDynamicSharedMemorySize, SM_SCAN3);
        attr_done = 1;
    }
    lstm_scan_mma<<<128, 512, SM_SCAN3>>>(c0, Whi, Whf, Whg, Who, out);
}